// round 16
// baseline (speedup 1.0000x reference)
#include <cuda_runtime.h>
#include <cuda_bf16.h>
#include <cstdint>
#include <math.h>

#define BSZ    4
#define SEQ    4096
#define DM     1024
#define NW     31
#define WIN    256
#define WSTRIDE 128
#define MROWS  (BSZ*SEQ)   // 16384
#define NBATCH (BSZ*NW)    // 124

// ---------------------------------------------------------------------------
// Scratch (__device__ globals; allocation-free per harness rules)
// ---------------------------------------------------------------------------
__device__ float g_sc[(size_t)NBATCH*WIN*WIN];     // fp32 scores
__device__ float g_v [(size_t)MROWS*DM];           // fp32 V-proj (pre-transpose)
__device__ float g_ow[(size_t)NBATCH*WIN*DM];      // fp32 per-window outputs
__device__ __nv_bfloat16 g_xh[(size_t)MROWS*DM], g_xl[(size_t)MROWS*DM];  // x prepacked
__device__ __nv_bfloat16 g_qh[(size_t)MROWS*DM], g_ql[(size_t)MROWS*DM];  // Q hi/lo
__device__ __nv_bfloat16 g_kh[(size_t)MROWS*DM], g_kl[(size_t)MROWS*DM];  // K hi/lo
__device__ __nv_bfloat16 g_vh[(size_t)MROWS*DM], g_vl[(size_t)MROWS*DM];  // V^T hi/lo
__device__ __nv_bfloat16 g_ph[(size_t)NBATCH*WIN*WIN], g_pl[(size_t)NBATCH*WIN*WIN]; // probs
__device__ __nv_bfloat16 g_ch[(size_t)MROWS*DM], g_cl[(size_t)MROWS*DM];  // combined
__device__ __nv_bfloat16 g_wh[4][(size_t)DM*DM], g_wl[4][(size_t)DM*DM];  // W^T

// ---------------------------------------------------------------------------
// helpers
// ---------------------------------------------------------------------------
__device__ __forceinline__ uint32_t smem_u32(const void* p){
    uint32_t a;
    asm("{ .reg .u64 t; cvta.to.shared.u64 t, %1; cvt.u32.u64 %0, t; }" : "=r"(a) : "l"(p));
    return a;
}
__device__ __forceinline__ void cp16(uint32_t dst, const void* src){
    asm volatile("cp.async.cg.shared.global [%0], [%1], 16;" :: "r"(dst), "l"(src) : "memory");
}
#define CP_COMMIT() asm volatile("cp.async.commit_group;" ::: "memory")
#define CP_WAIT0()  asm volatile("cp.async.wait_group 0;" ::: "memory")
#define CP_WAIT1()  asm volatile("cp.async.wait_group 1;" ::: "memory")

__device__ __forceinline__ void ldsm4(uint32_t* r, uint32_t addr){
    asm volatile("ldmatrix.sync.aligned.m8n8.x4.shared.b16 {%0,%1,%2,%3}, [%4];"
                 : "=r"(r[0]), "=r"(r[1]), "=r"(r[2]), "=r"(r[3]) : "r"(addr));
}
__device__ __forceinline__ void mma16816(float* c, const uint32_t* a, const uint32_t* b){
    asm volatile(
        "mma.sync.aligned.m16n8k16.row.col.f32.bf16.bf16.f32 "
        "{%0,%1,%2,%3}, {%4,%5,%6,%7}, {%8,%9}, {%0,%1,%2,%3};"
        : "+f"(c[0]), "+f"(c[1]), "+f"(c[2]), "+f"(c[3])
        : "r"(a[0]), "r"(a[1]), "r"(a[2]), "r"(a[3]), "r"(b[0]), "r"(b[1]));
}
__device__ __forceinline__ void split2(float a, float b, uint32_t& h, uint32_t& l){
    __nv_bfloat16 ha = __float2bfloat16_rn(a);
    __nv_bfloat16 hb = __float2bfloat16_rn(b);
    float ra = a - __bfloat162float(ha);
    float rb = b - __bfloat162float(hb);
    __nv_bfloat162 hv; hv.x = ha; hv.y = hb;
    __nv_bfloat162 lv; lv.x = __float2bfloat16_rn(ra); lv.y = __float2bfloat16_rn(rb);
    h = *reinterpret_cast<uint32_t*>(&hv);
    l = *reinterpret_cast<uint32_t*>(&lv);
}

// ---------------------------------------------------------------------------
// Split-bf16 HMMA GEMM, fully prepacked operands, 3-STAGE cp.async pipeline:
//   C = scale * (A @ B^T) + bias,  A = Ah+Al, B = Bh+Bl (bf16 pairs, K-contig)
// Block 128x256, BK=32, 8 warps (2x4), warp tile 64x64.
// smem per stage (49152 B, x3): Ah@0 (8KB), Al@8192, Bh@16384 (16KB), Bl@32768
// row = 32 bf16 = 64B = 4 x 16B groups, swizzle g ^= (row & 3)
// MODE 0: proj/out-proj  grid (N/256, M/128)
// MODE 1: scores         grid (1, 2, 124)
// MODE 2: P @ V          grid (4, 2, 124)
// EPI  0: fp32 C (+bias, *scale) | EPI 1: hi/lo bf16 Ch/Cl (+bias)
// ---------------------------------------------------------------------------
#define STAGE_SZ 49152
#define SMEM_SZ  (3*STAGE_SZ)

template<int MODE, int EPI>
__global__ __launch_bounds__(256)
void mma_gemm(const __nv_bfloat16* __restrict__ Ah, const __nv_bfloat16* __restrict__ Al, int lda,
              const __nv_bfloat16* __restrict__ Bh, const __nv_bfloat16* __restrict__ Bl, int ldb,
              float* __restrict__ C, __nv_bfloat16* __restrict__ Ch, __nv_bfloat16* __restrict__ Cl,
              int ldc, const float* __restrict__ bias, float scale, int K)
{
    extern __shared__ char sm[];
    const int tid  = threadIdx.x;
    const int lane = tid & 31;
    const int warp = tid >> 5;
    const int wm = warp >> 2;        // 0..1
    const int wn = warp & 3;         // 0..3
    const int row0 = blockIdx.y * 128;
    const int col0 = blockIdx.x * 256;

    const __nv_bfloat16 *Ahb, *Alb, *Bhb, *Blb;
    float* Cb = nullptr; __nv_bfloat16 *Chb = nullptr, *Clb = nullptr;
    if (MODE == 0) {
        Ahb = Ah + (size_t)row0 * lda;  Alb = Al + (size_t)row0 * lda;
        Bhb = Bh + (size_t)col0 * ldb;  Blb = Bl + (size_t)col0 * ldb;
        if (EPI == 0) Cb = C + (size_t)row0 * ldc + col0;
        else { Chb = Ch + (size_t)row0 * ldc + col0; Clb = Cl + (size_t)row0 * ldc + col0; }
    } else if (MODE == 1) {
        int bz = blockIdx.z; int b = bz / NW, w = bz - b * NW;
        size_t tok = (size_t)b * SEQ + (size_t)w * WSTRIDE;
        Ahb = Ah + (tok + row0) * DM;   Alb = Al + (tok + row0) * DM;
        Bhb = Bh + tok * DM;            Blb = Bl + tok * DM;
        Cb  = C + (size_t)bz * WIN * WIN + (size_t)row0 * WIN;
    } else {
        int bz = blockIdx.z; int b = bz / NW, w = bz - b * NW;
        Ahb = Ah + (size_t)bz * WIN * WIN + (size_t)row0 * WIN;
        Alb = Al + (size_t)bz * WIN * WIN + (size_t)row0 * WIN;
        size_t boff = (size_t)b * DM * SEQ + (size_t)w * WSTRIDE;
        Bhb = Bh + boff + (size_t)col0 * ldb;
        Blb = Bl + boff + (size_t)col0 * ldb;
        Cb  = C + (size_t)bz * WIN * DM + (size_t)row0 * DM + col0;
    }

    const uint32_t smb = smem_u32(sm);

    // ldmatrix source addresses (swizzled), per k-step
    const int rA = wm * 64 + (lane & 15);
    uint32_t aAddr[2];
    #pragma unroll
    for (int ks = 0; ks < 2; ks++)
        aAddr[ks] = smb + rA * 64 + (((ks * 2 + (lane >> 4)) ^ (rA & 3)) * 16);
    const int rB = wn * 64 + (lane & 7) + ((lane >> 4) & 1) * 8;
    uint32_t bAddr[2];
    #pragma unroll
    for (int ks = 0; ks < 2; ks++)
        bAddr[ks] = smb + 16384 + rB * 64 + (((ks * 2 + ((lane >> 3) & 1)) ^ (rB & 3)) * 16);

    // cp.async destinations: A 128 rows (2 per thread), B 256 rows (4 per thread)
    const int ar = tid >> 2;        // 0..63
    const int ag = tid & 3;
    uint32_t aSt[2];
    #pragma unroll
    for (int i = 0; i < 2; i++) {
        int row = ar + i * 64;
        aSt[i] = smb + row * 64 + ((ag ^ (row & 3)) * 16);
    }
    uint32_t bSt[4];
    #pragma unroll
    for (int i = 0; i < 4; i++) {
        int row = ar + i * 64;
        bSt[i] = smb + 16384 + row * 64 + ((ag ^ (row & 3)) * 16);
    }

    float acc[4][8][4];
    #pragma unroll
    for (int mi = 0; mi < 4; mi++)
        #pragma unroll
        for (int ni = 0; ni < 8; ni++)
            #pragma unroll
            for (int j = 0; j < 4; j++) acc[mi][ni][j] = 0.f;

    const int nch = K >> 5;   // BK = 32

    // issue all cp.asyncs for chunk kc into stage at offset off
    auto issue = [&](int kc, uint32_t off){
        #pragma unroll
        for (int i = 0; i < 2; i++) {
            int row = ar + i * 64;
            cp16(aSt[i] + off,        Ahb + (size_t)row * lda + kc + ag * 8);
            cp16(aSt[i] + off + 8192, Alb + (size_t)row * lda + kc + ag * 8);
        }
        #pragma unroll
        for (int i = 0; i < 4; i++) {
            int row = ar + i * 64;
            cp16(bSt[i] + off,         Bhb + (size_t)row * ldb + kc + ag * 8);
            cp16(bSt[i] + off + 16384, Blb + (size_t)row * ldb + kc + ag * 8);
        }
        CP_COMMIT();
    };

    // prologue: stages 0 and 1 in flight
    issue(0, 0);
    if (nch > 1) issue(32, STAGE_SZ);

    int stg = 0;   // stage index of chunk c
    for (int c = 0; c < nch; c++) {
        const uint32_t soff = (uint32_t)stg * STAGE_SZ;

        // oldest outstanding group (this chunk) must be done; keep 1 in flight
        if (c + 1 < nch) CP_WAIT1(); else CP_WAIT0();
        __syncthreads();

        // refill the stage freed at iteration c-1 (all warps are past it now)
        if (c + 2 < nch) {
            int ns = stg + 2; if (ns >= 3) ns -= 3;
            issue((c + 2) << 5, (uint32_t)ns * STAGE_SZ);
        }

        #pragma unroll
        for (int ks = 0; ks < 2; ks++) {
            uint32_t bh[4][4], bl[4][4];
            #pragma unroll
            for (int p = 0; p < 4; p++) {
                ldsm4(bh[p], bAddr[ks] + soff + p * 1024);
                ldsm4(bl[p], bAddr[ks] + soff + 16384 + p * 1024);
            }
            #pragma unroll
            for (int mi = 0; mi < 4; mi++) {
                uint32_t ah[4], al[4];
                ldsm4(ah, aAddr[ks] + soff + mi * 1024);
                ldsm4(al, aAddr[ks] + soff + 8192 + mi * 1024);
                #pragma unroll
                for (int p = 0; p < 4; p++) {
                    #pragma unroll
                    for (int h = 0; h < 2; h++) {
                        mma16816(acc[mi][2 * p + h], ah, &bh[p][2 * h]);
                        mma16816(acc[mi][2 * p + h], ah, &bl[p][2 * h]);
                        mma16816(acc[mi][2 * p + h], al, &bh[p][2 * h]);
                    }
                }
            }
        }

        if (++stg == 3) stg = 0;
    }

    // ---- epilogue ----
    const int erow = wm * 64 + (lane >> 2);
    const int ecol = wn * 64 + (lane & 3) * 2;
    #pragma unroll
    for (int ni = 0; ni < 8; ni++) {
        int cc = ecol + ni * 8;
        float2 bb = make_float2(0.f, 0.f);
        if (MODE == 0 && bias) bb = *(const float2*)(bias + col0 + cc);
        #pragma unroll
        for (int mi = 0; mi < 4; mi++) {
            int r = erow + mi * 16;
            float v0x = acc[mi][ni][0] * scale + bb.x;
            float v0y = acc[mi][ni][1] * scale + bb.y;
            float v1x = acc[mi][ni][2] * scale + bb.x;
            float v1y = acc[mi][ni][3] * scale + bb.y;
            if (EPI == 0) {
                *(float2*)(Cb + (size_t)r * ldc + cc)       = make_float2(v0x, v0y);
                *(float2*)(Cb + (size_t)(r + 8) * ldc + cc) = make_float2(v1x, v1y);
            } else {
                uint32_t h0, l0, h1, l1;
                split2(v0x, v0y, h0, l0);
                split2(v1x, v1y, h1, l1);
                *(uint32_t*)(Chb + (size_t)r * ldc + cc)       = h0;
                *(uint32_t*)(Clb + (size_t)r * ldc + cc)       = l0;
                *(uint32_t*)(Chb + (size_t)(r + 8) * ldc + cc) = h1;
                *(uint32_t*)(Clb + (size_t)(r + 8) * ldc + cc) = l1;
            }
        }
    }
}

// ---------------------------------------------------------------------------
// Prepack: transpose fp32 [R,C] -> hi/lo bf16 [C,R]  (per batch z)
// ---------------------------------------------------------------------------
__global__ __launch_bounds__(256)
void transpose_split(const float* __restrict__ in,
                     __nv_bfloat16* __restrict__ oh, __nv_bfloat16* __restrict__ ol,
                     int R, int C, long long zs)
{
    __shared__ float t[32][33];
    const float* ip = in + (size_t)blockIdx.z * zs;
    int r0 = blockIdx.y * 32, c0 = blockIdx.x * 32;
    int tx = threadIdx.x & 31, ty = threadIdx.x >> 5;
    #pragma unroll
    for (int i = ty; i < 32; i += 8)
        t[i][tx] = ip[(size_t)(r0 + i) * C + c0 + tx];
    __syncthreads();
    #pragma unroll
    for (int i = ty; i < 32; i += 8) {
        float x = t[tx][i];
        size_t o = (size_t)blockIdx.z * zs + (size_t)(c0 + i) * R + r0 + tx;
        __nv_bfloat16 h = __float2bfloat16_rn(x);
        oh[o] = h;
        ol[o] = __float2bfloat16_rn(x - __bfloat162float(h));
    }
}

// Prepack: elementwise fp32 -> hi/lo bf16
__global__ __launch_bounds__(256)
void cvt_split(const float* __restrict__ in,
               __nv_bfloat16* __restrict__ oh, __nv_bfloat16* __restrict__ ol, size_t n4)
{
    size_t i = (size_t)blockIdx.x * 256 + threadIdx.x;
    if (i >= n4) return;
    float4 v = ((const float4*)in)[i];
    uint32_t h0, l0, h1, l1;
    split2(v.x, v.y, h0, l0);
    split2(v.z, v.w, h1, l1);
    ((uint2*)oh)[i] = make_uint2(h0, h1);
    ((uint2*)ol)[i] = make_uint2(l0, l1);
}

// ---------------------------------------------------------------------------
// Row softmax: read fp32 scores, write hi/lo bf16 probs. One warp per row.
// ---------------------------------------------------------------------------
__global__ __launch_bounds__(256)
void softmax_rows()
{
    const int warp = (blockIdx.x * blockDim.x + threadIdx.x) >> 5;
    const int lane = threadIdx.x & 31;
    if (warp >= NBATCH * WIN) return;
    const float4* row = (const float4*)(g_sc + (size_t)warp * WIN);
    float4 v0 = row[lane];
    float4 v1 = row[lane + 32];
    float m = fmaxf(fmaxf(fmaxf(v0.x, v0.y), fmaxf(v0.z, v0.w)),
                    fmaxf(fmaxf(v1.x, v1.y), fmaxf(v1.z, v1.w)));
    #pragma unroll
    for (int off = 16; off > 0; off >>= 1)
        m = fmaxf(m, __shfl_xor_sync(0xFFFFFFFFu, m, off));
    v0.x = __expf(v0.x - m); v0.y = __expf(v0.y - m);
    v0.z = __expf(v0.z - m); v0.w = __expf(v0.w - m);
    v1.x = __expf(v1.x - m); v1.y = __expf(v1.y - m);
    v1.z = __expf(v1.z - m); v1.w = __expf(v1.w - m);
    float s = v0.x + v0.y + v0.z + v0.w + v1.x + v1.y + v1.z + v1.w;
    #pragma unroll
    for (int off = 16; off > 0; off >>= 1)
        s += __shfl_xor_sync(0xFFFFFFFFu, s, off);
    float inv = 1.f / s;
    v0.x *= inv; v0.y *= inv; v0.z *= inv; v0.w *= inv;
    v1.x *= inv; v1.y *= inv; v1.z *= inv; v1.w *= inv;

    uint32_t h0, l0, h1, l1;
    size_t base = (size_t)warp * WIN;
    split2(v0.x, v0.y, h0, l0); split2(v0.z, v0.w, h1, l1);
    *(uint2*)(g_ph + base + lane * 4) = make_uint2(h0, h1);
    *(uint2*)(g_pl + base + lane * 4) = make_uint2(l0, l1);
    split2(v1.x, v1.y, h0, l0); split2(v1.z, v1.w, h1, l1);
    *(uint2*)(g_ph + base + 128 + lane * 4) = make_uint2(h0, h1);
    *(uint2*)(g_pl + base + 128 + lane * 4) = make_uint2(l0, l1);
}

// ---------------------------------------------------------------------------
// Combine overlapping windows (mean), emit hi/lo bf16 for out-projection.
// ---------------------------------------------------------------------------
__global__ __launch_bounds__(256)
void combine_windows()
{
    const size_t nvec = (size_t)MROWS * DM / 4;
    size_t i = (size_t)blockIdx.x * blockDim.x + threadIdx.x;
    if (i >= nvec) return;
    size_t el = i * 4;
    int d = (int)(el % DM);
    size_t bt = el / DM;
    int t = (int)(bt % SEQ);
    int b = (int)(bt / SEQ);
    int w2 = t >> 7;
    int wlo = max(w2 - 1, 0);
    int whi = min(w2, NW - 1);
    float4 acc = make_float4(0.f, 0.f, 0.f, 0.f);
    for (int w = wlo; w <= whi; w++) {
        int pos = t - w * WSTRIDE;
        float4 x = *(const float4*)(g_ow + (((size_t)(b * NW + w) * WIN + pos) * DM + d));
        acc.x += x.x; acc.y += x.y; acc.z += x.z; acc.w += x.w;
    }
    float inv = 1.f / (float)(whi - wlo + 1);
    acc.x *= inv; acc.y *= inv; acc.z *= inv; acc.w *= inv;
    uint32_t h0, l0, h1, l1;
    split2(acc.x, acc.y, h0, l0);
    split2(acc.z, acc.w, h1, l1);
    *(uint2*)(g_ch + el) = make_uint2(h0, h1);
    *(uint2*)(g_cl + el) = make_uint2(l0, l1);
}

// ---------------------------------------------------------------------------
// launch — ordered so the Q-projection GEMM is launch index 3 (ncu capture slot)
// ---------------------------------------------------------------------------
extern "C" void kernel_launch(void* const* d_in, const int* in_sizes, int n_in,
                              void* d_out, int out_size)
{
    const float* x  = (const float*)d_in[0];
    const float* Wq = (const float*)d_in[1];
    const float* bq = (const float*)d_in[2];
    const float* Wk = (const float*)d_in[3];
    const float* bk = (const float*)d_in[4];
    const float* Wv = (const float*)d_in[5];
    const float* bv = (const float*)d_in[6];
    const float* Wo = (const float*)d_in[7];
    const float* bo = (const float*)d_in[8];
    float* out = (float*)d_out;

    float *sc, *v, *ow;
    __nv_bfloat16 *xh, *xl, *qh, *ql, *kh, *kl, *vh, *vl, *ph, *pl, *ch, *cl, *wh, *wl;
    cudaGetSymbolAddress((void**)&sc, g_sc);
    cudaGetSymbolAddress((void**)&v,  g_v);
    cudaGetSymbolAddress((void**)&ow, g_ow);
    cudaGetSymbolAddress((void**)&xh, g_xh);  cudaGetSymbolAddress((void**)&xl, g_xl);
    cudaGetSymbolAddress((void**)&qh, g_qh);  cudaGetSymbolAddress((void**)&ql, g_ql);
    cudaGetSymbolAddress((void**)&kh, g_kh);  cudaGetSymbolAddress((void**)&kl, g_kl);
    cudaGetSymbolAddress((void**)&vh, g_vh);  cudaGetSymbolAddress((void**)&vl, g_vl);
    cudaGetSymbolAddress((void**)&ph, g_ph);  cudaGetSymbolAddress((void**)&pl, g_pl);
    cudaGetSymbolAddress((void**)&ch, g_ch);  cudaGetSymbolAddress((void**)&cl, g_cl);
    cudaGetSymbolAddress((void**)&wh, g_wh);  cudaGetSymbolAddress((void**)&wl, g_wl);

    cudaFuncSetAttribute(mma_gemm<0,0>, cudaFuncAttributeMaxDynamicSharedMemorySize, SMEM_SZ);
    cudaFuncSetAttribute(mma_gemm<0,1>, cudaFuncAttributeMaxDynamicSharedMemorySize, SMEM_SZ);
    cudaFuncSetAttribute(mma_gemm<1,0>, cudaFuncAttributeMaxDynamicSharedMemorySize, SMEM_SZ);
    cudaFuncSetAttribute(mma_gemm<2,0>, cudaFuncAttributeMaxDynamicSharedMemorySize, SMEM_SZ);

    const size_t WSZ = (size_t)DM * DM;
    dim3 gW(DM / 32, DM / 32, 1);
    dim3 gProj(DM / 256, MROWS / 128, 1);   // (4, 128)

    // 0: x prepack
    cvt_split<<<(unsigned)(((size_t)MROWS * DM / 4 + 255) / 256), 256>>>(
        x, xh, xl, (size_t)MROWS * DM / 4);
    // 1,2: Wq, Wk prepack
    transpose_split<<<gW, 256>>>(Wq, wh + 0 * WSZ, wl + 0 * WSZ, DM, DM, 0);
    transpose_split<<<gW, 256>>>(Wk, wh + 1 * WSZ, wl + 1 * WSZ, DM, DM, 0);
    // 3: Q projection  <-- ncu capture slot
    mma_gemm<0,1><<<gProj, 256, SMEM_SZ>>>(xh, xl, DM, wh + 0 * WSZ, wl + 0 * WSZ, DM,
                                           nullptr, qh, ql, DM, bq, 1.f, DM);
    // 4,5: Wv, Wo prepack
    transpose_split<<<gW, 256>>>(Wv, wh + 2 * WSZ, wl + 2 * WSZ, DM, DM, 0);
    transpose_split<<<gW, 256>>>(Wo, wh + 3 * WSZ, wl + 3 * WSZ, DM, DM, 0);
    // 6,7: K, V projections
    mma_gemm<0,1><<<gProj, 256, SMEM_SZ>>>(xh, xl, DM, wh + 1 * WSZ, wl + 1 * WSZ, DM,
                                           nullptr, kh, kl, DM, bk, 1.f, DM);
    mma_gemm<0,0><<<gProj, 256, SMEM_SZ>>>(xh, xl, DM, wh + 2 * WSZ, wl + 2 * WSZ, DM,
                                           v, nullptr, nullptr, DM, bv, 1.f, DM);

    // 8: V transpose+split per batch: [b][token][d] -> [b][d][token]
    transpose_split<<<dim3(DM / 32, SEQ / 32, BSZ), 256>>>(
        v, vh, vl, SEQ, DM, (long long)SEQ * DM);

    // 9: Scores: 0.125 * Qw @ Kw^T
    mma_gemm<1,0><<<dim3(1, 2, NBATCH), 256, SMEM_SZ>>>(
        qh, ql, DM, kh, kl, DM, sc, nullptr, nullptr, WIN, nullptr, 0.125f, DM);

    // 10: softmax
    softmax_rows<<<(NBATCH * WIN + 7) / 8, 256>>>();

    // 11: O = P @ Vw
    mma_gemm<2,0><<<dim3(DM / 256, 2, NBATCH), 256, SMEM_SZ>>>(
        ph, pl, WIN, vh, vl, SEQ, ow, nullptr, nullptr, DM, nullptr, 1.f, WIN);

    // 12: combine
    combine_windows<<<(unsigned)(((size_t)MROWS * DM / 4 + 255) / 256), 256>>>();

    // 13: out projection
    mma_gemm<0,0><<<gProj, 256, SMEM_SZ>>>(ch, cl, DM, wh + 3 * WSZ, wl + 3 * WSZ, DM,
                                           out, nullptr, nullptr, DM, bo, 1.f, DM);
}

// round 17
// speedup vs baseline: 1.0166x; 1.0166x over previous
#include <cuda_runtime.h>
#include <cuda_bf16.h>
#include <cstdint>
#include <math.h>

#define BSZ    4
#define SEQ    4096
#define DM     1024
#define NW     31
#define WIN    256
#define WSTRIDE 128
#define MROWS  (BSZ*SEQ)   // 16384
#define NBATCH (BSZ*NW)    // 124

// ---------------------------------------------------------------------------
// Scratch (__device__ globals; allocation-free per harness rules)
// ---------------------------------------------------------------------------
__device__ float g_sc[(size_t)NBATCH*WIN*WIN];     // fp32 scores
__device__ float g_v [(size_t)MROWS*DM];           // fp32 V-proj (pre-transpose)
__device__ float g_ow[(size_t)NBATCH*WIN*DM];      // fp32 per-window outputs
__device__ __nv_bfloat16 g_xh[(size_t)MROWS*DM], g_xl[(size_t)MROWS*DM];  // x prepacked
__device__ __nv_bfloat16 g_qh[(size_t)MROWS*DM], g_ql[(size_t)MROWS*DM];  // Q hi/lo
__device__ __nv_bfloat16 g_kh[(size_t)MROWS*DM], g_kl[(size_t)MROWS*DM];  // K hi/lo
__device__ __nv_bfloat16 g_vh[(size_t)MROWS*DM], g_vl[(size_t)MROWS*DM];  // V^T hi/lo
__device__ __nv_bfloat16 g_ph[(size_t)NBATCH*WIN*WIN], g_pl[(size_t)NBATCH*WIN*WIN]; // probs
__device__ __nv_bfloat16 g_ch[(size_t)MROWS*DM], g_cl[(size_t)MROWS*DM];  // combined
__device__ __nv_bfloat16 g_wh[4][(size_t)DM*DM], g_wl[4][(size_t)DM*DM];  // W^T

// ---------------------------------------------------------------------------
// helpers
// ---------------------------------------------------------------------------
__device__ __forceinline__ uint32_t smem_u32(const void* p){
    uint32_t a;
    asm("{ .reg .u64 t; cvta.to.shared.u64 t, %1; cvt.u32.u64 %0, t; }" : "=r"(a) : "l"(p));
    return a;
}
__device__ __forceinline__ void cp16(uint32_t dst, const void* src){
    asm volatile("cp.async.cg.shared.global [%0], [%1], 16;" :: "r"(dst), "l"(src) : "memory");
}
#define CP_COMMIT() asm volatile("cp.async.commit_group;" ::: "memory")
#define CP_WAIT0()  asm volatile("cp.async.wait_group 0;" ::: "memory")
#define CP_WAIT1()  asm volatile("cp.async.wait_group 1;" ::: "memory")

__device__ __forceinline__ void ldsm4(uint32_t* r, uint32_t addr){
    asm volatile("ldmatrix.sync.aligned.m8n8.x4.shared.b16 {%0,%1,%2,%3}, [%4];"
                 : "=r"(r[0]), "=r"(r[1]), "=r"(r[2]), "=r"(r[3]) : "r"(addr));
}
__device__ __forceinline__ void mma16816(float* c, const uint32_t* a, const uint32_t* b){
    asm volatile(
        "mma.sync.aligned.m16n8k16.row.col.f32.bf16.bf16.f32 "
        "{%0,%1,%2,%3}, {%4,%5,%6,%7}, {%8,%9}, {%0,%1,%2,%3};"
        : "+f"(c[0]), "+f"(c[1]), "+f"(c[2]), "+f"(c[3])
        : "r"(a[0]), "r"(a[1]), "r"(a[2]), "r"(a[3]), "r"(b[0]), "r"(b[1]));
}
__device__ __forceinline__ void split2(float a, float b, uint32_t& h, uint32_t& l){
    __nv_bfloat16 ha = __float2bfloat16_rn(a);
    __nv_bfloat16 hb = __float2bfloat16_rn(b);
    float ra = a - __bfloat162float(ha);
    float rb = b - __bfloat162float(hb);
    __nv_bfloat162 hv; hv.x = ha; hv.y = hb;
    __nv_bfloat162 lv; lv.x = __float2bfloat16_rn(ra); lv.y = __float2bfloat16_rn(rb);
    h = *reinterpret_cast<uint32_t*>(&hv);
    l = *reinterpret_cast<uint32_t*>(&lv);
}

// ---------------------------------------------------------------------------
// Split-bf16 HMMA GEMM, prepacked operands, 3-stage cp.async pipeline,
// 512 THREADS / 16 WARPS (2x8), warp tile 64x32 — 4 warps/SMSP for latency
// hiding (R16 ncu: tensor=52.6%, occ=12.4% with 8 warps -> latency-bound).
//   C = scale * (A @ B^T) + bias,  A = Ah+Al, B = Bh+Bl (bf16 pairs, K-contig)
// Block 128x256, BK=32.
// smem per stage (49152 B, x3): Ah@0 (8KB), Al@8192, Bh@16384 (16KB), Bl@32768
// row = 32 bf16 = 64B = 4 x 16B groups, swizzle g ^= (row & 3)
// MODE 0: proj/out-proj  grid (N/256, M/128)
// MODE 1: scores         grid (1, 2, 124)
// MODE 2: P @ V          grid (4, 2, 124)
// EPI  0: fp32 C (+bias, *scale) | EPI 1: hi/lo bf16 Ch/Cl (+bias)
// ---------------------------------------------------------------------------
#define STAGE_SZ 49152
#define SMEM_SZ  (3*STAGE_SZ)
#define NTHR     512

template<int MODE, int EPI>
__global__ __launch_bounds__(NTHR)
void mma_gemm(const __nv_bfloat16* __restrict__ Ah, const __nv_bfloat16* __restrict__ Al, int lda,
              const __nv_bfloat16* __restrict__ Bh, const __nv_bfloat16* __restrict__ Bl, int ldb,
              float* __restrict__ C, __nv_bfloat16* __restrict__ Ch, __nv_bfloat16* __restrict__ Cl,
              int ldc, const float* __restrict__ bias, float scale, int K)
{
    extern __shared__ char sm[];
    const int tid  = threadIdx.x;
    const int lane = tid & 31;
    const int warp = tid >> 5;       // 0..15
    const int wm = warp >> 3;        // 0..1  (64 M-rows each)
    const int wn = warp & 7;         // 0..7  (32 N-cols each)
    const int row0 = blockIdx.y * 128;
    const int col0 = blockIdx.x * 256;

    const __nv_bfloat16 *Ahb, *Alb, *Bhb, *Blb;
    float* Cb = nullptr; __nv_bfloat16 *Chb = nullptr, *Clb = nullptr;
    if (MODE == 0) {
        Ahb = Ah + (size_t)row0 * lda;  Alb = Al + (size_t)row0 * lda;
        Bhb = Bh + (size_t)col0 * ldb;  Blb = Bl + (size_t)col0 * ldb;
        if (EPI == 0) Cb = C + (size_t)row0 * ldc + col0;
        else { Chb = Ch + (size_t)row0 * ldc + col0; Clb = Cl + (size_t)row0 * ldc + col0; }
    } else if (MODE == 1) {
        int bz = blockIdx.z; int b = bz / NW, w = bz - b * NW;
        size_t tok = (size_t)b * SEQ + (size_t)w * WSTRIDE;
        Ahb = Ah + (tok + row0) * DM;   Alb = Al + (tok + row0) * DM;
        Bhb = Bh + tok * DM;            Blb = Bl + tok * DM;
        Cb  = C + (size_t)bz * WIN * WIN + (size_t)row0 * WIN;
    } else {
        int bz = blockIdx.z; int b = bz / NW, w = bz - b * NW;
        Ahb = Ah + (size_t)bz * WIN * WIN + (size_t)row0 * WIN;
        Alb = Al + (size_t)bz * WIN * WIN + (size_t)row0 * WIN;
        size_t boff = (size_t)b * DM * SEQ + (size_t)w * WSTRIDE;
        Bhb = Bh + boff + (size_t)col0 * ldb;
        Blb = Bl + boff + (size_t)col0 * ldb;
        Cb  = C + (size_t)bz * WIN * DM + (size_t)row0 * DM + col0;
    }

    const uint32_t smb = smem_u32(sm);

    // ldmatrix source addresses (swizzled), per k-step
    const int rA = wm * 64 + (lane & 15);
    uint32_t aAddr[2];
    #pragma unroll
    for (int ks = 0; ks < 2; ks++)
        aAddr[ks] = smb + rA * 64 + (((ks * 2 + (lane >> 4)) ^ (rA & 3)) * 16);
    const int rB = wn * 32 + (lane & 7) + ((lane >> 4) & 1) * 8;
    uint32_t bAddr[2];
    #pragma unroll
    for (int ks = 0; ks < 2; ks++)
        bAddr[ks] = smb + 16384 + rB * 64 + (((ks * 2 + ((lane >> 3) & 1)) ^ (rB & 3)) * 16);

    // cp.async destinations: 512 threads, A 128 rows (1/thread), B 256 rows (2/thread)
    const int ar = tid >> 2;        // 0..127
    const int ag = tid & 3;
    const uint32_t aSt = smb + ar * 64 + ((ag ^ (ar & 3)) * 16);
    uint32_t bSt[2];
    #pragma unroll
    for (int i = 0; i < 2; i++) {
        int row = ar + i * 128;
        bSt[i] = smb + 16384 + row * 64 + ((ag ^ (row & 3)) * 16);
    }

    float acc[4][4][4];
    #pragma unroll
    for (int mi = 0; mi < 4; mi++)
        #pragma unroll
        for (int ni = 0; ni < 4; ni++)
            #pragma unroll
            for (int j = 0; j < 4; j++) acc[mi][ni][j] = 0.f;

    const int nch = K >> 5;   // BK = 32

    // issue all cp.asyncs for chunk kc into stage at offset off (6 per thread)
    auto issue = [&](int kc, uint32_t off){
        cp16(aSt + off,        Ahb + (size_t)ar * lda + kc + ag * 8);
        cp16(aSt + off + 8192, Alb + (size_t)ar * lda + kc + ag * 8);
        #pragma unroll
        for (int i = 0; i < 2; i++) {
            int row = ar + i * 128;
            cp16(bSt[i] + off,         Bhb + (size_t)row * ldb + kc + ag * 8);
            cp16(bSt[i] + off + 16384, Blb + (size_t)row * ldb + kc + ag * 8);
        }
        CP_COMMIT();
    };

    // prologue: stages 0 and 1 in flight
    issue(0, 0);
    if (nch > 1) issue(32, STAGE_SZ);

    int stg = 0;   // stage index of chunk c
    for (int c = 0; c < nch; c++) {
        const uint32_t soff = (uint32_t)stg * STAGE_SZ;

        if (c + 1 < nch) CP_WAIT1(); else CP_WAIT0();
        __syncthreads();

        // refill the stage freed at iteration c-1 (all warps are past it now)
        if (c + 2 < nch) {
            int ns = stg + 2; if (ns >= 3) ns -= 3;
            issue((c + 2) << 5, (uint32_t)ns * STAGE_SZ);
        }

        #pragma unroll
        for (int ks = 0; ks < 2; ks++) {
            uint32_t bh[2][4], bl[2][4];
            #pragma unroll
            for (int p = 0; p < 2; p++) {
                ldsm4(bh[p], bAddr[ks] + soff + p * 1024);
                ldsm4(bl[p], bAddr[ks] + soff + 16384 + p * 1024);
            }
            #pragma unroll
            for (int mi = 0; mi < 4; mi++) {
                uint32_t ah[4], al[4];
                ldsm4(ah, aAddr[ks] + soff + mi * 1024);
                ldsm4(al, aAddr[ks] + soff + 8192 + mi * 1024);
                #pragma unroll
                for (int p = 0; p < 2; p++) {
                    #pragma unroll
                    for (int h = 0; h < 2; h++) {
                        mma16816(acc[mi][2 * p + h], ah, &bh[p][2 * h]);
                        mma16816(acc[mi][2 * p + h], ah, &bl[p][2 * h]);
                        mma16816(acc[mi][2 * p + h], al, &bh[p][2 * h]);
                    }
                }
            }
        }

        if (++stg == 3) stg = 0;
    }

    // ---- epilogue ----
    const int erow = wm * 64 + (lane >> 2);
    const int ecol = wn * 32 + (lane & 3) * 2;
    #pragma unroll
    for (int ni = 0; ni < 4; ni++) {
        int cc = ecol + ni * 8;
        float2 bb = make_float2(0.f, 0.f);
        if (MODE == 0 && bias) bb = *(const float2*)(bias + col0 + cc);
        #pragma unroll
        for (int mi = 0; mi < 4; mi++) {
            int r = erow + mi * 16;
            float v0x = acc[mi][ni][0] * scale + bb.x;
            float v0y = acc[mi][ni][1] * scale + bb.y;
            float v1x = acc[mi][ni][2] * scale + bb.x;
            float v1y = acc[mi][ni][3] * scale + bb.y;
            if (EPI == 0) {
                *(float2*)(Cb + (size_t)r * ldc + cc)       = make_float2(v0x, v0y);
                *(float2*)(Cb + (size_t)(r + 8) * ldc + cc) = make_float2(v1x, v1y);
            } else {
                uint32_t h0, l0, h1, l1;
                split2(v0x, v0y, h0, l0);
                split2(v1x, v1y, h1, l1);
                *(uint32_t*)(Chb + (size_t)r * ldc + cc)       = h0;
                *(uint32_t*)(Clb + (size_t)r * ldc + cc)       = l0;
                *(uint32_t*)(Chb + (size_t)(r + 8) * ldc + cc) = h1;
                *(uint32_t*)(Clb + (size_t)(r + 8) * ldc + cc) = l1;
            }
        }
    }
}

// ---------------------------------------------------------------------------
// Prepack: transpose fp32 [R,C] -> hi/lo bf16 [C,R]  (per batch z)
// ---------------------------------------------------------------------------
__global__ __launch_bounds__(256)
void transpose_split(const float* __restrict__ in,
                     __nv_bfloat16* __restrict__ oh, __nv_bfloat16* __restrict__ ol,
                     int R, int C, long long zs)
{
    __shared__ float t[32][33];
    const float* ip = in + (size_t)blockIdx.z * zs;
    int r0 = blockIdx.y * 32, c0 = blockIdx.x * 32;
    int tx = threadIdx.x & 31, ty = threadIdx.x >> 5;
    #pragma unroll
    for (int i = ty; i < 32; i += 8)
        t[i][tx] = ip[(size_t)(r0 + i) * C + c0 + tx];
    __syncthreads();
    #pragma unroll
    for (int i = ty; i < 32; i += 8) {
        float x = t[tx][i];
        size_t o = (size_t)blockIdx.z * zs + (size_t)(c0 + i) * R + r0 + tx;
        __nv_bfloat16 h = __float2bfloat16_rn(x);
        oh[o] = h;
        ol[o] = __float2bfloat16_rn(x - __bfloat162float(h));
    }
}

// Prepack: elementwise fp32 -> hi/lo bf16
__global__ __launch_bounds__(256)
void cvt_split(const float* __restrict__ in,
               __nv_bfloat16* __restrict__ oh, __nv_bfloat16* __restrict__ ol, size_t n4)
{
    size_t i = (size_t)blockIdx.x * 256 + threadIdx.x;
    if (i >= n4) return;
    float4 v = ((const float4*)in)[i];
    uint32_t h0, l0, h1, l1;
    split2(v.x, v.y, h0, l0);
    split2(v.z, v.w, h1, l1);
    ((uint2*)oh)[i] = make_uint2(h0, h1);
    ((uint2*)ol)[i] = make_uint2(l0, l1);
}

// ---------------------------------------------------------------------------
// Row softmax: read fp32 scores, write hi/lo bf16 probs. One warp per row.
// ---------------------------------------------------------------------------
__global__ __launch_bounds__(256)
void softmax_rows()
{
    const int warp = (blockIdx.x * blockDim.x + threadIdx.x) >> 5;
    const int lane = threadIdx.x & 31;
    if (warp >= NBATCH * WIN) return;
    const float4* row = (const float4*)(g_sc + (size_t)warp * WIN);
    float4 v0 = row[lane];
    float4 v1 = row[lane + 32];
    float m = fmaxf(fmaxf(fmaxf(v0.x, v0.y), fmaxf(v0.z, v0.w)),
                    fmaxf(fmaxf(v1.x, v1.y), fmaxf(v1.z, v1.w)));
    #pragma unroll
    for (int off = 16; off > 0; off >>= 1)
        m = fmaxf(m, __shfl_xor_sync(0xFFFFFFFFu, m, off));
    v0.x = __expf(v0.x - m); v0.y = __expf(v0.y - m);
    v0.z = __expf(v0.z - m); v0.w = __expf(v0.w - m);
    v1.x = __expf(v1.x - m); v1.y = __expf(v1.y - m);
    v1.z = __expf(v1.z - m); v1.w = __expf(v1.w - m);
    float s = v0.x + v0.y + v0.z + v0.w + v1.x + v1.y + v1.z + v1.w;
    #pragma unroll
    for (int off = 16; off > 0; off >>= 1)
        s += __shfl_xor_sync(0xFFFFFFFFu, s, off);
    float inv = 1.f / s;
    v0.x *= inv; v0.y *= inv; v0.z *= inv; v0.w *= inv;
    v1.x *= inv; v1.y *= inv; v1.z *= inv; v1.w *= inv;

    uint32_t h0, l0, h1, l1;
    size_t base = (size_t)warp * WIN;
    split2(v0.x, v0.y, h0, l0); split2(v0.z, v0.w, h1, l1);
    *(uint2*)(g_ph + base + lane * 4) = make_uint2(h0, h1);
    *(uint2*)(g_pl + base + lane * 4) = make_uint2(l0, l1);
    split2(v1.x, v1.y, h0, l0); split2(v1.z, v1.w, h1, l1);
    *(uint2*)(g_ph + base + 128 + lane * 4) = make_uint2(h0, h1);
    *(uint2*)(g_pl + base + 128 + lane * 4) = make_uint2(l0, l1);
}

// ---------------------------------------------------------------------------
// Combine overlapping windows (mean), emit hi/lo bf16 for out-projection.
// ---------------------------------------------------------------------------
__global__ __launch_bounds__(256)
void combine_windows()
{
    const size_t nvec = (size_t)MROWS * DM / 4;
    size_t i = (size_t)blockIdx.x * blockDim.x + threadIdx.x;
    if (i >= nvec) return;
    size_t el = i * 4;
    int d = (int)(el % DM);
    size_t bt = el / DM;
    int t = (int)(bt % SEQ);
    int b = (int)(bt / SEQ);
    int w2 = t >> 7;
    int wlo = max(w2 - 1, 0);
    int whi = min(w2, NW - 1);
    float4 acc = make_float4(0.f, 0.f, 0.f, 0.f);
    for (int w = wlo; w <= whi; w++) {
        int pos = t - w * WSTRIDE;
        float4 x = *(const float4*)(g_ow + (((size_t)(b * NW + w) * WIN + pos) * DM + d));
        acc.x += x.x; acc.y += x.y; acc.z += x.z; acc.w += x.w;
    }
    float inv = 1.f / (float)(whi - wlo + 1);
    acc.x *= inv; acc.y *= inv; acc.z *= inv; acc.w *= inv;
    uint32_t h0, l0, h1, l1;
    split2(acc.x, acc.y, h0, l0);
    split2(acc.z, acc.w, h1, l1);
    *(uint2*)(g_ch + el) = make_uint2(h0, h1);
    *(uint2*)(g_cl + el) = make_uint2(l0, l1);
}

// ---------------------------------------------------------------------------
// launch — Q-projection GEMM at launch index 3 (ncu capture slot)
// ---------------------------------------------------------------------------
extern "C" void kernel_launch(void* const* d_in, const int* in_sizes, int n_in,
                              void* d_out, int out_size)
{
    const float* x  = (const float*)d_in[0];
    const float* Wq = (const float*)d_in[1];
    const float* bq = (const float*)d_in[2];
    const float* Wk = (const float*)d_in[3];
    const float* bk = (const float*)d_in[4];
    const float* Wv = (const float*)d_in[5];
    const float* bv = (const float*)d_in[6];
    const float* Wo = (const float*)d_in[7];
    const float* bo = (const float*)d_in[8];
    float* out = (float*)d_out;

    float *sc, *v, *ow;
    __nv_bfloat16 *xh, *xl, *qh, *ql, *kh, *kl, *vh, *vl, *ph, *pl, *ch, *cl, *wh, *wl;
    cudaGetSymbolAddress((void**)&sc, g_sc);
    cudaGetSymbolAddress((void**)&v,  g_v);
    cudaGetSymbolAddress((void**)&ow, g_ow);
    cudaGetSymbolAddress((void**)&xh, g_xh);  cudaGetSymbolAddress((void**)&xl, g_xl);
    cudaGetSymbolAddress((void**)&qh, g_qh);  cudaGetSymbolAddress((void**)&ql, g_ql);
    cudaGetSymbolAddress((void**)&kh, g_kh);  cudaGetSymbolAddress((void**)&kl, g_kl);
    cudaGetSymbolAddress((void**)&vh, g_vh);  cudaGetSymbolAddress((void**)&vl, g_vl);
    cudaGetSymbolAddress((void**)&ph, g_ph);  cudaGetSymbolAddress((void**)&pl, g_pl);
    cudaGetSymbolAddress((void**)&ch, g_ch);  cudaGetSymbolAddress((void**)&cl, g_cl);
    cudaGetSymbolAddress((void**)&wh, g_wh);  cudaGetSymbolAddress((void**)&wl, g_wl);

    cudaFuncSetAttribute(mma_gemm<0,0>, cudaFuncAttributeMaxDynamicSharedMemorySize, SMEM_SZ);
    cudaFuncSetAttribute(mma_gemm<0,1>, cudaFuncAttributeMaxDynamicSharedMemorySize, SMEM_SZ);
    cudaFuncSetAttribute(mma_gemm<1,0>, cudaFuncAttributeMaxDynamicSharedMemorySize, SMEM_SZ);
    cudaFuncSetAttribute(mma_gemm<2,0>, cudaFuncAttributeMaxDynamicSharedMemorySize, SMEM_SZ);

    const size_t WSZ = (size_t)DM * DM;
    dim3 gW(DM / 32, DM / 32, 1);
    dim3 gProj(DM / 256, MROWS / 128, 1);   // (4, 128)

    // 0: x prepack
    cvt_split<<<(unsigned)(((size_t)MROWS * DM / 4 + 255) / 256), 256>>>(
        x, xh, xl, (size_t)MROWS * DM / 4);
    // 1,2: Wq, Wk prepack
    transpose_split<<<gW, 256>>>(Wq, wh + 0 * WSZ, wl + 0 * WSZ, DM, DM, 0);
    transpose_split<<<gW, 256>>>(Wk, wh + 1 * WSZ, wl + 1 * WSZ, DM, DM, 0);
    // 3: Q projection  <-- ncu capture slot
    mma_gemm<0,1><<<gProj, NTHR, SMEM_SZ>>>(xh, xl, DM, wh + 0 * WSZ, wl + 0 * WSZ, DM,
                                            nullptr, qh, ql, DM, bq, 1.f, DM);
    // 4,5: Wv, Wo prepack
    transpose_split<<<gW, 256>>>(Wv, wh + 2 * WSZ, wl + 2 * WSZ, DM, DM, 0);
    transpose_split<<<gW, 256>>>(Wo, wh + 3 * WSZ, wl + 3 * WSZ, DM, DM, 0);
    // 6,7: K, V projections
    mma_gemm<0,1><<<gProj, NTHR, SMEM_SZ>>>(xh, xl, DM, wh + 1 * WSZ, wl + 1 * WSZ, DM,
                                            nullptr, kh, kl, DM, bk, 1.f, DM);
    mma_gemm<0,0><<<gProj, NTHR, SMEM_SZ>>>(xh, xl, DM, wh + 2 * WSZ, wl + 2 * WSZ, DM,
                                            v, nullptr, nullptr, DM, bv, 1.f, DM);

    // 8: V transpose+split per batch: [b][token][d] -> [b][d][token]
    transpose_split<<<dim3(DM / 32, SEQ / 32, BSZ), 256>>>(
        v, vh, vl, SEQ, DM, (long long)SEQ * DM);

    // 9: Scores: 0.125 * Qw @ Kw^T
    mma_gemm<1,0><<<dim3(1, 2, NBATCH), NTHR, SMEM_SZ>>>(
        qh, ql, DM, kh, kl, DM, sc, nullptr, nullptr, WIN, nullptr, 0.125f, DM);

    // 10: softmax
    softmax_rows<<<(NBATCH * WIN + 7) / 8, 256>>>();

    // 11: O = P @ Vw
    mma_gemm<2,0><<<dim3(DM / 256, 2, NBATCH), NTHR, SMEM_SZ>>>(
        ph, pl, WIN, vh, vl, SEQ, ow, nullptr, nullptr, DM, nullptr, 1.f, WIN);

    // 12: combine
    combine_windows<<<(unsigned)(((size_t)MROWS * DM / 4 + 255) / 256), 256>>>();

    // 13: out projection
    mma_gemm<0,0><<<gProj, NTHR, SMEM_SZ>>>(ch, cl, DM, wh + 3 * WSZ, wl + 3 * WSZ, DM,
                                            out, nullptr, nullptr, DM, bo, 1.f, DM);
}